// round 2
// baseline (speedup 1.0000x reference)
#include <cuda_runtime.h>

// CTC loss forward (alpha DP), faithful to tf.nn.ctc_loss with blank_index=0.
// B=1024, T=256, C=128, L=32 -> S = 2L+1 = 65 extended states.
// One CTA per batch element, 128 threads (one per class).
// Per time step: coalesced row load (prefetched), block sum-exp reduce for
// log-softmax normalizer, then threads 0..64 update their alpha state from a
// ping-pong shared buffer. 2 __syncthreads per step.

#define TN 256
#define CN 128
#define LN 32
#define SN 65
#define PADV 127
#define NEGF (-1e30f)

__global__ __launch_bounds__(128) void ctc_alpha_kernel(
    const int* __restrict__ yt, const float* __restrict__ yp,
    float* __restrict__ out)
{
    const int b = blockIdx.x;
    const int tid = threadIdx.x;
    const float* __restrict__ row = yp + (size_t)b * TN * CN;
    const int* __restrict__ lab = yt + b * LN;

    __shared__ float xs[CN];          // this step's logits (for gather at ext symbols)
    __shared__ float ws[4];           // per-warp exp sums
    __shared__ float alpha[2][SN + 3];// ping-pong alpha, padded
    __shared__ int len_sh;

    // label length = count of non-PAD entries
    if (tid < 32) {
        unsigned m = __ballot_sync(0xffffffffu, lab[tid] != PADV);
        if (tid == 0) len_sh = __popc(m);
    }

    // per-state constants (thread tid owns extended state s=tid, s<65)
    const int s = tid;
    int sym = 0;         // ext[s]: blank for even s, label for odd s
    bool skip = false;   // s-2 -> s transition allowed
    if (s < SN && (s & 1)) {
        sym = lab[s >> 1];
        if (s >= 3) skip = (sym != lab[(s - 2) >> 1]);
    }

    float x = row[tid];  // prefetched logits for current step
    int cur = 0;

    for (int t = 0; t < TN; ++t) {
        xs[tid] = x;
        // sum of exp over C (no max-shift: logits ~N(0,1), fp32-safe)
        float e = __expf(x);
        #pragma unroll
        for (int off = 16; off; off >>= 1)
            e += __shfl_xor_sync(0xffffffffu, e, off);
        if ((tid & 31) == 0) ws[tid >> 5] = e;
        __syncthreads();                        // xs, ws visible; prev alpha write visible
        const float logZ = __logf(ws[0] + ws[1] + ws[2] + ws[3]);

        // prefetch next row while we do the DP math
        float xn = 0.f;
        if (t + 1 < TN) xn = row[(t + 1) * CN + tid];

        float nv = NEGF;
        if (s < SN) {
            const float lp = xs[sym] - logZ;    // log-softmax at ext symbol
            if (t == 0) {
                nv = (s < 2) ? lp : NEGF;       // alpha0
            } else {
                const float a0 = alpha[cur][s];
                const float a1 = (s >= 1) ? alpha[cur][s - 1] : NEGF;
                const float a2 = skip ? alpha[cur][s - 2] : NEGF;
                const float m = fmaxf(a0, fmaxf(a1, a2));
                const float sum = __expf(a0 - m) + __expf(a1 - m) + __expf(a2 - m);
                nv = lp + m + __logf(sum);
            }
        }
        __syncthreads();                        // all reads of xs & alpha[cur] done
        if (s < SN) alpha[cur ^ 1][s] = nv;
        cur ^= 1;
        x = xn;
    }

    __syncthreads();                            // final alpha writes visible
    if (tid == 0) {
        const int len = len_sh;
        const float a = alpha[cur][2 * len];
        const float c = (len > 0) ? alpha[cur][2 * len - 1] : NEGF;
        const float m = fmaxf(a, c);
        const float ll = m + __logf(__expf(a - m) + __expf(c - m));
        out[b] = -ll;
    }
}

extern "C" void kernel_launch(void* const* d_in, const int* in_sizes, int n_in,
                              void* d_out, int out_size) {
    const int* y_true = (const int*)d_in[0];     // [1024, 32] int32
    const float* y_pred = (const float*)d_in[1]; // [1024, 256, 128] float32
    float* out = (float*)d_out;                  // [1024] float32
    const int B = in_sizes[0] / LN;              // 1024
    ctc_alpha_kernel<<<B, 128>>>(y_true, y_pred, out);
}

// round 4
// speedup vs baseline: 2.2577x; 2.2577x over previous
#include <cuda_runtime.h>

// CTC loss forward (alpha DP), warp-synchronous: one warp per batch element.
// B=1024, T=256, C=128, L=32 -> S=65 extended states.
// Lane l owns states s=2l+1 (label lab[l]) and s=2l+2 (blank); state 0 is a
// pure self-loop (replicated scalar add). Zero __syncthreads, zero smem.
// Softmax over C=128 via float4 per lane + butterfly shuffle. lp is computed
// one step ahead (software pipeline) and rows prefetched 4 steps ahead so the
// cross-iteration chain is only the DP logaddexp. All math in log2 domain
// (EX2/LG2 MUFU ops), converted to natural log at the end.

#define TN 256
#define CN 128
#define LN 32
#define PADV 127
#define NEGF (-1e30f)
#define LOG2E 1.4426950408889634f
#define NLN2 0.6931471805599453f

__device__ __forceinline__ float ex2(float x) {
    float r; asm("ex2.approx.f32 %0, %1;" : "=f"(r) : "f"(x)); return r;
}
__device__ __forceinline__ float lg2(float x) {
    float r; asm("lg2.approx.f32 %0, %1;" : "=f"(r) : "f"(x)); return r;
}

__device__ __forceinline__ float lae2(float a, float b) {       // log2-add-exp2
    float m = fmaxf(a, b);
    return m + lg2(ex2(a - m) + ex2(b - m));
}
__device__ __forceinline__ float lae3(float a, float b, float c) {
    float m = fmaxf(a, fmaxf(b, c));
    return m + lg2(ex2(a - m) + ex2(b - m) + ex2(c - m));
}

struct LP { float b, l; };  // base-2 log-softmax at blank / this lane's label

// Compute lp for one row (v = lane's 4 classes). src/comp locate lab[l].
__device__ __forceinline__ LP row_lp(float4 v, int src, int comp) {
    const unsigned FULL = 0xffffffffu;
    float x0 = v.x * LOG2E, x1 = v.y * LOG2E, x2 = v.z * LOG2E, x3 = v.w * LOG2E;
    float s = ex2(x0) + ex2(x1) + ex2(x2) + ex2(x3);
    #pragma unroll
    for (int o = 16; o; o >>= 1) s += __shfl_xor_sync(FULL, s, o);
    float logZ = lg2(s);
    float gb = __shfl_sync(FULL, x0, 0);          // class 0 = blank
    float v0 = __shfl_sync(FULL, x0, src);
    float v1 = __shfl_sync(FULL, x1, src);
    float v2 = __shfl_sync(FULL, x2, src);
    float v3 = __shfl_sync(FULL, x3, src);
    float gl = (comp & 2) ? ((comp & 1) ? v3 : v2) : ((comp & 1) ? v1 : v0);
    LP r; r.b = gb - logZ; r.l = gl - logZ; return r;
}

__global__ __launch_bounds__(32) void ctc_warp_kernel(
    const int* __restrict__ yt, const float* __restrict__ yp,
    float* __restrict__ out)
{
    const unsigned FULL = 0xffffffffu;
    const int b = blockIdx.x;
    const int l = threadIdx.x;
    const float4* __restrict__ row = (const float4*)(yp + (size_t)b * TN * CN);

    const int lab = yt[b * LN + l];
    const unsigned mask = __ballot_sync(FULL, lab != PADV);
    const int len = __popc(mask);
    const int labp = __shfl_up_sync(FULL, lab, 1);
    const bool skip = (l >= 1) && (lab != labp);
    const int src = lab >> 2, comp = lab & 3;

    // t=0: init alpha
    float4 v0r = row[l];
    LP lp0 = row_lp(v0r, src, comp);
    float a0 = lp0.b;                       // state 0 (replicated, uniform)
    float a_odd = (l == 0) ? lp0.l : NEGF;  // state 2l+1
    float a_even = NEGF;                    // state 2l+2

    // prefetch ring: rows t+1 .. t+4
    float4 ring[4];
    #pragma unroll
    for (int i = 0; i < 4; ++i) ring[i] = row[(1 + i) * 32 + l];
    LP lp = row_lp(ring[0], src, comp);     // lp(1)

    #pragma unroll 4
    for (int t = 1; t < TN; ++t) {
        // refill slot that held row t with row t+4
        int tload = (t + 4 < TN) ? (t + 4) : (TN - 1);
        ring[(t - 1) & 3] = row[tload * 32 + l];

        // DP step t using lp(t) (computed last iteration)
        float po = __shfl_up_sync(FULL, a_odd, 1);   // alpha[2l-1]
        float pe = __shfl_up_sync(FULL, a_even, 1);  // alpha[2l]
        po = (l == 0) ? NEGF : po;
        pe = (l == 0) ? a0 : pe;
        float n_odd  = lp.l + lae3(a_odd, pe, skip ? po : NEGF);
        float n_even = lp.b + lae2(a_even, a_odd);
        a0 += lp.b;
        a_odd = n_odd; a_even = n_even;

        // compute lp(t+1) from ring (independent of DP; overlaps next chain)
        lp = row_lp(ring[t & 3], src, comp);
    }

    // loglik ends at states 2*len (even, lane len-1) and 2*len-1 (odd, lane len-1)
    float ve = __shfl_sync(FULL, a_even, (len - 1) & 31);
    float vo = __shfl_sync(FULL, a_odd, (len - 1) & 31);
    if (l == 0) {
        float ll2 = (len >= 1) ? lae2(ve, vo) : a0;
        out[b] = -ll2 * NLN2;
    }
}

extern "C" void kernel_launch(void* const* d_in, const int* in_sizes, int n_in,
                              void* d_out, int out_size) {
    const int* y_true = (const int*)d_in[0];     // [1024, 32] int32
    const float* y_pred = (const float*)d_in[1]; // [1024, 256, 128] float32
    float* out = (float*)d_out;                  // [1024] float32
    const int B = in_sizes[0] / LN;              // 1024
    ctc_warp_kernel<<<B, 32>>>(y_true, y_pred, out);
}